// round 16
// baseline (speedup 1.0000x reference)
#include <cuda_runtime.h>
#include <math.h>
#include <float.h>

// Problem constants (fixed by the dataset)
#define P_PRED 3
#define E_EV   128
#define CHUNKS 2
#define TPB    256
#define NWARP  (TPB / 32)

#define TIME_TOL 0.1f
#define DECAY    0.8f
#define RES_D    0.03

// Scratch (no device allocation allowed anywhere).
__device__ double g_partials[2048];
__device__ int    g_counter = 0;

__device__ __forceinline__ float final_intensity(float raw, float base) {
    return (raw >= 0.0f) ? fmaxf(raw, base) : __expf(raw);
}

__device__ __forceinline__ float lam_of(float w, float feat, float b) {
    float raw = __fadd_rn(b, __fmul_rn(w, feat));   // mirror ref: mul then add
    return final_intensity(raw, b);
}

// Branchless count of events with (t - st[e]) > 0.1f on sorted st[0..128).
// Bit-exact vs the reference's f32 predicate (monotone in te).
__device__ __forceinline__ int cut_count(const float* __restrict__ st, float t) {
    int c = 0;
#pragma unroll
    for (int step = 64; step >= 1; step >>= 1)
        if ((t - st[c + step - 1]) > TIME_TOL) c += step;
    if ((t - st[c]) > TIME_TOL) ++c;    // handles c == 128 exactly
    return c;
}

__device__ __forceinline__ double warp_reduce_f64(double v) {
#pragma unroll
    for (int o = 16; o >= 1; o >>= 1)
        v += __shfl_down_sync(0xffffffffu, v, o);
    return v;
}

__global__ __launch_bounds__(TPB)
void hawkes_fused(const float* __restrict__ event_times,
                  const float* __restrict__ event_mask,
                  const float* __restrict__ base,
                  const float* __restrict__ weight,
                  const void*  __restrict__ tmax_ptr,
                  float* __restrict__ out) {
    const int s     = blockIdx.x / CHUNKS;
    const int chunk = blockIdx.x % CHUNKS;
    const int tid   = threadIdx.x;
    const int NB    = gridDim.x;
    const int wid   = tid >> 5, lane = tid & 31;

    __shared__ float st[P_PRED][E_EV + 1];    // sorted times + FLT_MAX sentinel
    __shared__ float sm[P_PRED][E_EV];        // masks
    __shared__ float pref[P_PRED][E_EV + 1];  // f32 prefix of m*exp(0.8*te)
    __shared__ float sb[P_PRED], sw[P_PRED];
    __shared__ double wred[NWARP];

    // ---- hoisted: tmax load + grid count (integer fast path) ----
    int tmax_i = *(const int*)tmax_ptr;
    int G;
    if (tmax_i > 0 && tmax_i < 1000000) {
        G = (tmax_i * 100 + 2) / 3;           // ceil(T/0.03) for integer T
    } else {
        G = (int)ceil((double)(*(const float*)tmax_ptr) / RES_D);
    }

    // ---- fused vectorized load + f32 scan: warp w owns predicate w ----
    if (wid < P_PRED) {
        const float4* et4 = (const float4*)(event_times + ((size_t)s * P_PRED + wid) * E_EV);
        const float4* em4 = (const float4*)(event_mask  + ((size_t)s * P_PRED + wid) * E_EV);
        float4 tv = et4[lane];
        float4 mv = em4[lane];
        int e0 = lane * 4;
        st[wid][e0 + 0] = tv.x;  st[wid][e0 + 1] = tv.y;
        st[wid][e0 + 2] = tv.z;  st[wid][e0 + 3] = tv.w;
        sm[wid][e0 + 0] = mv.x;  sm[wid][e0 + 1] = mv.y;
        sm[wid][e0 + 2] = mv.z;  sm[wid][e0 + 3] = mv.w;

        // 4 independent exps, then one 5-step shfl scan of thread-local sums.
        float v0 = __fmul_rn(mv.x, __expf(__fmul_rn(DECAY, tv.x)));
        float v1 = __fmul_rn(mv.y, __expf(__fmul_rn(DECAY, tv.y)));
        float v2 = __fmul_rn(mv.z, __expf(__fmul_rn(DECAY, tv.z)));
        float v3 = __fmul_rn(mv.w, __expf(__fmul_rn(DECAY, tv.w)));
        float s01 = __fadd_rn(v0, v1);
        float s012 = __fadd_rn(s01, v2);
        float lsum = __fadd_rn(s012, v3);

        float inc = lsum;
#pragma unroll
        for (int o = 1; o < 32; o <<= 1) {
            float n = __shfl_up_sync(0xffffffffu, inc, o);
            if (lane >= o) inc = __fadd_rn(inc, n);
        }
        float ex = inc - lsum;      // exclusive prefix for this thread's 4 slots
        pref[wid][e0 + 1] = __fadd_rn(ex, v0);
        pref[wid][e0 + 2] = __fadd_rn(ex, s01);
        pref[wid][e0 + 3] = __fadd_rn(ex, s012);
        pref[wid][e0 + 4] = inc;
        if (lane == 0) {
            pref[wid][0] = 0.0f;
            st[wid][E_EV] = FLT_MAX;          // advance-loop sentinel
        }
    } else if (wid == 3 && lane < P_PRED) {
        sb[lane] = base[lane];
        sw[lane] = weight[lane];
    }
    __syncthreads();

    const float b0 = sb[0], b1 = sb[1], b2 = sb[2];
    const float w0 = sw[0], w1 = sw[1], w2 = sw[2];

    // ---- integral term: contiguous per-thread range + incremental advance ----
    const int per = (G + CHUNKS - 1) / CHUNKS;
    const int gs  = chunk * per;
    const int ge  = min(gs + per, G);
    const int npt = (per + TPB - 1) / TPB;
    const int r0  = gs + tid * npt;
    const int r1  = min(r0 + npt, ge);

    float acc_int = 0.0f;     // <= 4 small terms: f32 is plenty
    if (r0 < r1) {
        // One bit-exact binary search for the first point (3 interleaved chains).
        float t0 = (float)((double)r0 * RES_D);
        int c0 = 0, c1 = 0, c2 = 0;
#pragma unroll
        for (int step = 64; step >= 1; step >>= 1) {
            if ((t0 - st[0][c0 + step - 1]) > TIME_TOL) c0 += step;
            if ((t0 - st[1][c1 + step - 1]) > TIME_TOL) c1 += step;
            if ((t0 - st[2][c2 + step - 1]) > TIME_TOL) c2 += step;
        }
        if ((t0 - st[0][c0]) > TIME_TOL) ++c0;
        if ((t0 - st[1][c1]) > TIME_TOL) ++c1;
        if ((t0 - st[2][c2]) > TIME_TOL) ++c2;

        for (int g = r0; g < r1; ++g) {
            float t = (float)((double)g * RES_D);   // matches np.arange(f64) -> f32
            // Monotone incremental advance with the identical predicate.
            while ((t - st[0][c0]) > TIME_TOL) ++c0;
            while ((t - st[1][c1]) > TIME_TOL) ++c1;
            while ((t - st[2][c2]) > TIME_TOL) ++c2;

            float edk = __expf(__fmul_rn(-DECAY, t));
            float k0 = __fmul_rn(edk, pref[0][c0]);
            float k1 = __fmul_rn(edk, pref[1][c1]);
            float k2 = __fmul_rn(edk, pref[2][c2]);

            // BODY = [[0,1,1],[1,0,0],[1,0,0]]
            float l0 = lam_of(w0, __fadd_rn(k1, k2), b0);
            float l1 = lam_of(w1, k0, b1);
            float l2 = lam_of(w2, k0, b2);
            acc_int += (l0 + l1 + l2);
        }
    }

    double acc = -(double)RES_D * (double)acc_int;

    // ---- log-sum term: each head's own event times, eq >= 1, mask > 0 ----
    const int QPER = (P_PRED * E_EV) / CHUNKS;   // 192
    if (tid < QPER) {
        int q = chunk * QPER + tid;
        int h = q >> 7, eq = q & 127;
        if (eq >= 1 && sm[h][eq] > 0.0f) {
            float tq = st[h][eq];
            float edk = __expf(__fmul_rn(-DECAY, tq));
            float feat;
            if (h == 0) {
                float k1 = __fmul_rn(edk, pref[1][cut_count(st[1], tq)]);
                float k2 = __fmul_rn(edk, pref[2][cut_count(st[2], tq)]);
                feat = __fadd_rn(k1, k2);
            } else {
                feat = __fmul_rn(edk, pref[0][cut_count(st[0], tq)]);
            }
            float bh = (h == 0) ? b0 : (h == 1) ? b1 : b2;
            float wh = (h == 0) ? w0 : (h == 1) ? w1 : w2;
            acc += (double)logf(lam_of(wh, feat, bh));
        }
    }

    // ---- deterministic block reduce; tail handled entirely by warp 0 ----
    double v = warp_reduce_f64(acc);
    if (lane == 0) wred[wid] = v;
    __syncthreads();
    if (wid == 0) {
        double a = (lane < NWARP) ? wred[lane] : 0.0;
#pragma unroll
        for (int o = 4; o >= 1; o >>= 1)
            a += __shfl_down_sync(0xffffffffu, a, o);
        int old = 0;
        if (lane == 0) {
            g_partials[blockIdx.x] = a;
            __threadfence();
            old = atomicAdd(&g_counter, 1);
        }
        // Broadcast within warp 0 only — no block barrier needed.
        old = __shfl_sync(0xffffffffu, old, 0);

        if (old == NB - 1) {
            // Last block: warp 0 alone does the fixed-order final reduce.
            __threadfence();
            double t = 0.0;
#pragma unroll
            for (int i = 0; i < 4; ++i) {          // NB = 128 = 4 * 32
                int idx = i * 32 + lane;
                if (idx < NB) t += g_partials[idx];
            }
            t = warp_reduce_f64(t);
            if (lane == 0) {
                out[0] = (float)t;
                g_counter = 0;   // reset for next graph replay
            }
        }
    }
}

extern "C" void kernel_launch(void* const* d_in, const int* in_sizes, int n_in,
                              void* d_out, int out_size) {
    const float* event_times = (const float*)d_in[0];
    const float* event_mask  = (const float*)d_in[1];
    const float* base        = (const float*)d_in[2];
    const float* weight      = (const float*)d_in[3];
    const void*  tmax        = d_in[4];

    int S = in_sizes[0] / (P_PRED * E_EV);
    int nblocks = S * CHUNKS;

    hawkes_fused<<<nblocks, TPB>>>(event_times, event_mask, base, weight, tmax,
                                   (float*)d_out);
}

// round 17
// speedup vs baseline: 1.0239x; 1.0239x over previous
#include <cuda_runtime.h>
#include <math.h>
#include <float.h>

// Problem constants (fixed by the dataset)
#define P_PRED 3
#define E_EV   128
#define CHUNKS 2
#define TPB    256
#define NWARP  (TPB / 32)

#define TIME_TOL 0.1f
#define DECAY    0.8f
#define RES_D    0.03

// Scratch (no device allocation allowed anywhere).
__device__ double g_partials[2048];
__device__ int    g_counter = 0;

__device__ __forceinline__ float final_intensity(float raw, float base) {
    return (raw >= 0.0f) ? fmaxf(raw, base) : __expf(raw);
}

__device__ __forceinline__ float lam_of(float w, float feat, float b) {
    float raw = __fadd_rn(b, __fmul_rn(w, feat));   // mirror ref: mul then add
    return final_intensity(raw, b);
}

// Branchless count of events with (t - st[e]) > 0.1f on sorted st[0..128).
// Bit-exact vs the reference's f32 predicate (monotone in te).
__device__ __forceinline__ int cut_count(const float* __restrict__ st, float t) {
    int c = 0;
#pragma unroll
    for (int step = 64; step >= 1; step >>= 1)
        if ((t - st[c + step - 1]) > TIME_TOL) c += step;
    if ((t - st[c]) > TIME_TOL) ++c;    // handles c == 128 exactly
    return c;
}

__device__ __forceinline__ double warp_reduce_f64(double v) {
#pragma unroll
    for (int o = 16; o >= 1; o >>= 1)
        v += __shfl_down_sync(0xffffffffu, v, o);
    return v;
}

__global__ __launch_bounds__(TPB)
void hawkes_fused(const float* __restrict__ event_times,
                  const float* __restrict__ event_mask,
                  const float* __restrict__ base,
                  const float* __restrict__ weight,
                  const void*  __restrict__ tmax_ptr,
                  float* __restrict__ out) {
    const int s     = blockIdx.x / CHUNKS;
    const int chunk = blockIdx.x % CHUNKS;
    const int tid   = threadIdx.x;
    const int NB    = gridDim.x;
    const int wid   = tid >> 5, lane = tid & 31;

    __shared__ float st[P_PRED][E_EV + 1];    // sorted times + FLT_MAX sentinel
    __shared__ float sm[P_PRED][E_EV];        // masks
    __shared__ float pref[P_PRED][E_EV + 1];  // f32 prefix of m*exp(0.8*te)
    __shared__ float sb[P_PRED], sw[P_PRED];
    __shared__ double wred[NWARP];
    __shared__ int islast;

    // ---- hoisted: tmax load + grid count (overlaps the scan below) ----
    int tmax_i = *(const int*)tmax_ptr;
    if (!(tmax_i > 0 && tmax_i < 1000000)) tmax_i = (int)(*(const float*)tmax_ptr);
    const int G = (int)ceil((double)tmax_i / RES_D);

    // ---- fused vectorized load + f32 scan: warp w owns predicate w ----
    if (wid < P_PRED) {
        const float4* et4 = (const float4*)(event_times + ((size_t)s * P_PRED + wid) * E_EV);
        const float4* em4 = (const float4*)(event_mask  + ((size_t)s * P_PRED + wid) * E_EV);
        float4 tv = et4[lane];
        float4 mv = em4[lane];
        int e0 = lane * 4;
        st[wid][e0 + 0] = tv.x;  st[wid][e0 + 1] = tv.y;
        st[wid][e0 + 2] = tv.z;  st[wid][e0 + 3] = tv.w;
        sm[wid][e0 + 0] = mv.x;  sm[wid][e0 + 1] = mv.y;
        sm[wid][e0 + 2] = mv.z;  sm[wid][e0 + 3] = mv.w;

        // 4 independent exps, then one 5-step shfl scan of thread-local sums.
        float v0 = __fmul_rn(mv.x, __expf(__fmul_rn(DECAY, tv.x)));
        float v1 = __fmul_rn(mv.y, __expf(__fmul_rn(DECAY, tv.y)));
        float v2 = __fmul_rn(mv.z, __expf(__fmul_rn(DECAY, tv.z)));
        float v3 = __fmul_rn(mv.w, __expf(__fmul_rn(DECAY, tv.w)));
        float s01 = __fadd_rn(v0, v1);
        float s012 = __fadd_rn(s01, v2);
        float lsum = __fadd_rn(s012, v3);

        float inc = lsum;
#pragma unroll
        for (int o = 1; o < 32; o <<= 1) {
            float n = __shfl_up_sync(0xffffffffu, inc, o);
            if (lane >= o) inc = __fadd_rn(inc, n);
        }
        float ex = inc - lsum;      // exclusive prefix for this thread's 4 slots
        pref[wid][e0 + 1] = __fadd_rn(ex, v0);
        pref[wid][e0 + 2] = __fadd_rn(ex, s01);
        pref[wid][e0 + 3] = __fadd_rn(ex, s012);
        pref[wid][e0 + 4] = inc;
        if (lane == 0) {
            pref[wid][0] = 0.0f;
            st[wid][E_EV] = FLT_MAX;          // advance-loop sentinel
        }
    } else if (wid == 3 && lane < P_PRED) {
        sb[lane] = base[lane];
        sw[lane] = weight[lane];
    }
    __syncthreads();

    const float b0 = sb[0], b1 = sb[1], b2 = sb[2];
    const float w0 = sw[0], w1 = sw[1], w2 = sw[2];

    // ---- integral term: contiguous per-thread range + incremental advance ----
    const int per = (G + CHUNKS - 1) / CHUNKS;
    const int gs  = chunk * per;
    const int ge  = min(gs + per, G);
    const int npt = (per + TPB - 1) / TPB;
    const int r0  = gs + tid * npt;
    const int r1  = min(r0 + npt, ge);

    float acc_int = 0.0f;     // <= 4 small terms: f32 is plenty
    if (r0 < r1) {
        // One bit-exact binary search for the first point (3 interleaved chains).
        float t0 = (float)((double)r0 * RES_D);
        int c0 = 0, c1 = 0, c2 = 0;
#pragma unroll
        for (int step = 64; step >= 1; step >>= 1) {
            if ((t0 - st[0][c0 + step - 1]) > TIME_TOL) c0 += step;
            if ((t0 - st[1][c1 + step - 1]) > TIME_TOL) c1 += step;
            if ((t0 - st[2][c2 + step - 1]) > TIME_TOL) c2 += step;
        }
        if ((t0 - st[0][c0]) > TIME_TOL) ++c0;
        if ((t0 - st[1][c1]) > TIME_TOL) ++c1;
        if ((t0 - st[2][c2]) > TIME_TOL) ++c2;

        for (int g = r0; g < r1; ++g) {
            float t = (float)((double)g * RES_D);   // matches np.arange(f64) -> f32
            // Monotone incremental advance with the identical predicate.
            while ((t - st[0][c0]) > TIME_TOL) ++c0;
            while ((t - st[1][c1]) > TIME_TOL) ++c1;
            while ((t - st[2][c2]) > TIME_TOL) ++c2;

            float edk = __expf(__fmul_rn(-DECAY, t));
            float k0 = __fmul_rn(edk, pref[0][c0]);
            float k1 = __fmul_rn(edk, pref[1][c1]);
            float k2 = __fmul_rn(edk, pref[2][c2]);

            // BODY = [[0,1,1],[1,0,0],[1,0,0]]
            float l0 = lam_of(w0, __fadd_rn(k1, k2), b0);
            float l1 = lam_of(w1, k0, b1);
            float l2 = lam_of(w2, k0, b2);
            acc_int += (l0 + l1 + l2);
        }
    }

    double acc = -(double)RES_D * (double)acc_int;

    // ---- log-sum term: each head's own event times, eq >= 1, mask > 0 ----
    const int QPER = (P_PRED * E_EV) / CHUNKS;   // 192
    if (tid < QPER) {
        int q = chunk * QPER + tid;
        int h = q >> 7, eq = q & 127;
        if (eq >= 1 && sm[h][eq] > 0.0f) {
            float tq = st[h][eq];
            float edk = __expf(__fmul_rn(-DECAY, tq));
            float feat;
            if (h == 0) {
                float k1 = __fmul_rn(edk, pref[1][cut_count(st[1], tq)]);
                float k2 = __fmul_rn(edk, pref[2][cut_count(st[2], tq)]);
                feat = __fadd_rn(k1, k2);
            } else {
                feat = __fmul_rn(edk, pref[0][cut_count(st[0], tq)]);
            }
            float bh = (h == 0) ? b0 : (h == 1) ? b1 : b2;
            float wh = (h == 0) ? w0 : (h == 1) ? w1 : w2;
            acc += (double)logf(lam_of(wh, feat, bh));
        }
    }

    // ---- deterministic shuffle-based block reduce ----
    double v = warp_reduce_f64(acc);
    if (lane == 0) wred[wid] = v;
    __syncthreads();
    if (wid == 0) {
        double a = (lane < NWARP) ? wred[lane] : 0.0;
#pragma unroll
        for (int o = 4; o >= 1; o >>= 1)
            a += __shfl_down_sync(0xffffffffu, a, o);
        if (lane == 0) {
            g_partials[blockIdx.x] = a;
            __threadfence();
            int old = atomicAdd(&g_counter, 1);
            islast = (old == NB - 1) ? 1 : 0;
        }
    }
    __syncthreads();

    // ---- last block: fixed-order deterministic final reduce ----
    if (islast) {
        __threadfence();
        double a = (tid < NB) ? g_partials[tid] : 0.0;
        a = warp_reduce_f64(a);
        if (lane == 0) wred[wid] = a;
        __syncthreads();
        if (wid == 0) {
            double b = (lane < NWARP) ? wred[lane] : 0.0;
#pragma unroll
            for (int o = 4; o >= 1; o >>= 1)
                b += __shfl_down_sync(0xffffffffu, b, o);
            if (lane == 0) {
                out[0] = (float)b;
                g_counter = 0;   // reset for next graph replay
            }
        }
    }
}

extern "C" void kernel_launch(void* const* d_in, const int* in_sizes, int n_in,
                              void* d_out, int out_size) {
    const float* event_times = (const float*)d_in[0];
    const float* event_mask  = (const float*)d_in[1];
    const float* base        = (const float*)d_in[2];
    const float* weight      = (const float*)d_in[3];
    const void*  tmax        = d_in[4];

    int S = in_sizes[0] / (P_PRED * E_EV);
    int nblocks = S * CHUNKS;

    hawkes_fused<<<nblocks, TPB>>>(event_times, event_mask, base, weight, tmax,
                                   (float*)d_out);
}